// round 7
// baseline (speedup 1.0000x reference)
#include <cuda_runtime.h>
#include <math.h>

typedef unsigned long long ull;

#define DTs   0.2f
#define TILEX 52
#define TILEY 54
#define HALOX 6
#define HALOY 5
#define NTX   32
#define NTY   16
#define RPT   4

// ---- packed f32x2 helpers (sm_103a) ----
__device__ __forceinline__ ull fma2(ull a, ull b, ull c) {
    ull d; asm("fma.rn.f32x2 %0, %1, %2, %3;" : "=l"(d) : "l"(a), "l"(b), "l"(c)); return d;
}
__device__ __forceinline__ ull mul2(ull a, ull b) {
    ull d; asm("mul.rn.f32x2 %0, %1, %2;" : "=l"(d) : "l"(a), "l"(b)); return d;
}
__device__ __forceinline__ ull add2(ull a, ull b) {
    ull d; asm("add.rn.f32x2 %0, %1, %2;" : "=l"(d) : "l"(a), "l"(b)); return d;
}
__device__ __forceinline__ ull pk(float lo, float hi) {
    ull r; asm("mov.b64 %0, {%1, %2};" : "=l"(r) : "f"(lo), "f"(hi)); return r;
}
__device__ __forceinline__ float2 up(ull v) {
    float2 t; asm("mov.b64 {%0, %1}, %2;" : "=f"(t.x), "=f"(t.y) : "l"(v)); return t;
}

struct TrueT  { static constexpr bool value = true;  };
struct FalseT { static constexpr bool value = false; };

__global__ __launch_bounds__(NTX * NTY, 2)
void vib7(const float* __restrict__ force,
          const float* __restrict__ cw,
          const float* __restrict__ omega,
          const float* __restrict__ zeta,
          float* __restrict__ out,
          int H, int W, int C)
{
    __shared__ ull xb[2][34][32];   // double-buffered warp-boundary rows (+guards)
    __shared__ ull fs[64][32];      // F*DT pairs

    const int tx = threadIdx.x;
    const int ty = threadIdx.y;
    const int rb = ty * RPT;
    const int plane = blockIdx.z;
    const int c = plane % C;
    const int bx = blockIdx.x, by = blockIdx.y;
    const bool edge = (bx == 0) | (bx == 4) | (by == 0) | (by == 4);

    const int gx0 = bx * TILEX - HALOX;   // even
    const int gy0 = by * TILEY - HALOY;

    // per-channel params
    const float o  = __ldg(omega + c);
    const float zt = __ldg(zeta + c);
    const float w  = log1pf(expf(o));
    const float z  = 1.0f / (1.0f + expf(-zt));
    const float w2 = w * w;
    const float c1s = 1.0f - 2.0f * z * w * DTs;
    const ull c1p   = pk(c1s, c1s);
    const ull cbdtp = pk(-w2 * DTs, -w2 * DTs);
    const ull DTp   = pk(DTs, DTs);

    ull kp[9];
    #pragma unroll
    for (int j = 0; j < 9; j++) {
        const float kv = __ldg(cw + c * 9 + j) * DTs;
        kp[j] = pk(kv, kv);
    }

    const float* fp = force + (size_t)plane * (H * W);
    const int gc0 = gx0 + 2 * tx;                    // even -> 8B-aligned pair
    const bool cok = (unsigned)gc0 < (unsigned)W;    // pair all-or-nothing

    ull vv[RPT], xc[RPT], msk[RPT];

    // ---- init: step 1 analytic (v1 = F*DT, x1 = v1*DT) ----
    #pragma unroll
    for (int i = 0; i < RPT; i++) {
        const int gr = gy0 + rb + i;
        float2 f = make_float2(0.0f, 0.0f);
        if (!edge) {
            f = *reinterpret_cast<const float2*>(fp + gr * W + gc0);
        } else {
            const bool ok = cok && ((unsigned)gr < (unsigned)H);
            if (ok) f = *reinterpret_cast<const float2*>(fp + gr * W + gc0);
            const float m = ok ? 1.0f : 0.0f;
            msk[i] = pk(m, m);
        }
        const ull F2 = pk(f.x * DTs, f.y * DTs);
        fs[rb + i][tx] = F2;
        vv[i] = F2;
        xc[i] = mul2(F2, DTp);
    }
    xb[0][2 * ty + 1][tx] = xc[0];
    xb[0][2 * ty + 2][tx] = xc[RPT - 1];
    if (ty == 0) {
        xb[0][0][tx] = 0ULL; xb[0][33][tx] = 0ULL;
        xb[1][0][tx] = 0ULL; xb[1][33][tx] = 0ULL;
    }
    __syncthreads();

    // ---- mainloop: 5 fused conv+update steps, 1 barrier each (round-5 form) ----
    auto mainloop = [&](auto MASKC) {
        constexpr bool MASK = decltype(MASKC)::value;
        #pragma unroll 1
        for (int s = 0; s < 5; s++) {
            ull (*curb)[32] = xb[s & 1];
            ull (*nxtb)[32] = xb[(s & 1) ^ 1];

            const ull T = curb[2 * ty][tx];        // row rb-1
            const ull B = curb[2 * ty + 3][tx];    // row rb+RPT
            const float2 t2 = up(T);
            ull Lt = pk(__shfl_up_sync(0xffffffffu, t2.y, 1), t2.x);
            ull Rt = pk(t2.y, __shfl_down_sync(0xffffffffu, t2.x, 1));
            ull Ct = T;
            const float2 m2 = up(xc[0]);
            ull Lm = pk(__shfl_up_sync(0xffffffffu, m2.y, 1), m2.x);
            ull Rm = pk(m2.y, __shfl_down_sync(0xffffffffu, m2.x, 1));

            // prefetch row-0's below line (line 1) and its F
            ull Cb = xc[1];
            float2 b2 = up(Cb);
            float sl = __shfl_up_sync(0xffffffffu, b2.y, 1);
            float sr = __shfl_down_sync(0xffffffffu, b2.x, 1);
            ull Fi = fs[rb][tx];

            #pragma unroll
            for (int i = 0; i < RPT; i++) {
                const ull Lb = pk(sl, b2.x);
                const ull Rb = pk(b2.y, sr);

                // prefetch next row's below-line + F (hide SHFL/LDS latency)
                ull Cb_n = 0; float2 b2n; float sln = 0.f, srn = 0.f; ull Fn = 0;
                if (i < RPT - 1) {
                    Cb_n = (i + 1 < RPT - 1) ? xc[i + 2] : B;
                    b2n = up(Cb_n);
                    sln = __shfl_up_sync(0xffffffffu, b2n.y, 1);
                    srn = __shfl_down_sync(0xffffffffu, b2n.x, 1);
                    Fn = fs[rb + i + 1][tx];
                }

                ull acc0 = fma2(cbdtp, xc[i], Fi);
                acc0 = fma2(kp[0], Lt, acc0);
                acc0 = fma2(kp[1], Ct, acc0);
                acc0 = fma2(kp[2], Rt, acc0);
                acc0 = fma2(kp[3], Lm, acc0);
                acc0 = fma2(kp[4], xc[i], acc0);
                ull acc1 = mul2(kp[5], Rm);
                acc1 = fma2(kp[6], Lb, acc1);
                acc1 = fma2(kp[7], Cb, acc1);
                acc1 = fma2(kp[8], Rb, acc1);
                acc1 = fma2(c1p, vv[i], acc1);
                vv[i] = add2(acc0, acc1);

                ull xn = fma2(vv[i], DTp, xc[i]);
                if (MASK) xn = mul2(xn, msk[i]);

                Lt = Lm; Ct = xc[i]; Rt = Rm; Lm = Lb; Rm = Rb;
                xc[i] = xn;
                Cb = Cb_n; b2 = b2n; sl = sln; sr = srn; Fi = Fn;
            }
            nxtb[2 * ty + 1][tx] = xc[0];
            nxtb[2 * ty + 2][tx] = xc[RPT - 1];
            __syncthreads();
        }
    };

    if (edge) mainloop(TrueT{});
    else      mainloop(FalseT{});

    // ---- packed energy output: region cols [6,57] -> one STG.64 per row ----
    float* op = out + (size_t)plane * (H * W);
    const ull hp   = pk(0.5f, 0.5f);
    const ull hw2p = pk(0.5f * w2, 0.5f * w2);
    const bool cstore = (tx >= 3) && (tx <= 28) && cok;   // region cols 6..57
    #pragma unroll
    for (int i = 0; i < RPT; i++) {
        const int r = rb + i;
        if (r < HALOY || r > 58) continue;                // region rows 5..58 valid
        const int gr = gy0 + r;
        if (!cstore || (unsigned)gr >= (unsigned)H) continue;
        const ull vv2 = mul2(vv[i], vv[i]);
        const ull xx2 = mul2(xc[i], xc[i]);
        const ull e   = fma2(hw2p, xx2, mul2(hp, vv2));
        *reinterpret_cast<ull*>(op + (size_t)gr * W + gc0) = e;
    }
}

extern "C" void kernel_launch(void* const* d_in, const int* in_sizes, int n_in,
                              void* d_out, int out_size)
{
    const float* force = (const float*)d_in[0];
    const float* cw    = (const float*)d_in[1];
    const float* omega = (const float*)d_in[2];
    const float* zeta  = (const float*)d_in[3];
    float* out = (float*)d_out;

    const int H = 256, W = 256;
    const int C = in_sizes[2];
    const int planes = in_sizes[0] / (H * W);

    dim3 block(NTX, NTY);
    vib7<<<dim3(5, 5, planes), block>>>(force, cw, omega, zeta, out, H, W, C);
}

// round 8
// speedup vs baseline: 1.3565x; 1.3565x over previous
#include <cuda_runtime.h>
#include <math.h>

typedef unsigned long long ull;

#define DTs   0.2f
#define TILEX 52
#define TILEY 54
#define NTHR  256

// ---- packed f32x2 helpers (sm_103a) ----
__device__ __forceinline__ ull fma2(ull a, ull b, ull c) {
    ull d; asm("fma.rn.f32x2 %0, %1, %2, %3;" : "=l"(d) : "l"(a), "l"(b), "l"(c)); return d;
}
__device__ __forceinline__ ull mul2(ull a, ull b) {
    ull d; asm("mul.rn.f32x2 %0, %1, %2;" : "=l"(d) : "l"(a), "l"(b)); return d;
}
__device__ __forceinline__ ull add2(ull a, ull b) {
    ull d; asm("add.rn.f32x2 %0, %1, %2;" : "=l"(d) : "l"(a), "l"(b)); return d;
}
__device__ __forceinline__ ull pk(float lo, float hi) {
    ull r; asm("mov.b64 %0, {%1, %2};" : "=l"(r) : "f"(lo), "f"(hi)); return r;
}
__device__ __forceinline__ float2 up(ull v) {
    float2 t; asm("mov.b64 {%0, %1}, %2;" : "=f"(t.x), "=f"(t.y) : "l"(v)); return t;
}

struct Line { ull La, Ca, Cb, Rb, Mid; };

// Build a stencil line from a lane's two pairs: a=(c0,c1), b=(c2,c3).
// Edge scalars from neighbor lanes within the 16-lane half (width=16).
__device__ __forceinline__ Line make_line(ull a, ull b) {
    const float2 af = up(a), bf = up(b);
    const float el = __shfl_up_sync(0xffffffffu, bf.y, 1, 16);
    const float er = __shfl_down_sync(0xffffffffu, af.x, 1, 16);
    Line L;
    L.La  = pk(el, af.x);
    L.Ca  = a;
    L.Cb  = b;
    L.Mid = pk(af.y, bf.x);
    L.Rb  = pk(bf.y, er);
    return L;
}

struct TrueT  { static constexpr bool value = true;  };
struct FalseT { static constexpr bool value = false; };

__global__ __launch_bounds__(NTHR, 3)
void vib8(const float* __restrict__ force,
          const float* __restrict__ cw,
          const float* __restrict__ omega,
          const float* __restrict__ zeta,
          float* __restrict__ out,
          int H, int W, int C)
{
    // boundary rows: 16 bands -> slots 1..32, guards 0 and 33; ulonglong2 = (pair a, pair b)
    __shared__ ulonglong2 bnd[2][34][16];   // 17.4 KB
    __shared__ ulonglong2 fs[64][16];       // 16 KB : F*DT pairs

    const int tid  = threadIdx.x;
    const int lane = tid & 31;
    const int l16  = lane & 15;
    const int bi   = ((tid >> 5) << 1) | ((lane >> 4) & 1);  // band 0..15
    const int rb   = bi * 4;

    const int plane = blockIdx.z;
    const int c = plane % C;
    const int bx = blockIdx.x, by = blockIdx.y;
    const bool edge = (bx == 0) | (bx == 4) | (by == 0) | (by == 4);

    const int gx0 = bx * TILEX - 6;
    const int gy0 = by * TILEY - 5;

    // per-channel params
    const float o  = __ldg(omega + c);
    const float zt = __ldg(zeta + c);
    const float w  = log1pf(expf(o));
    const float z  = 1.0f / (1.0f + expf(-zt));
    const float w2 = w * w;
    const float c1s = 1.0f - 2.0f * z * w * DTs;
    const ull c1p   = pk(c1s, c1s);
    const ull cbdtp = pk(-w2 * DTs, -w2 * DTs);
    const ull DTp   = pk(DTs, DTs);

    ull kp[9];
    #pragma unroll
    for (int j = 0; j < 9; j++) {
        const float kv = __ldg(cw + c * 9 + j) * DTs;
        kp[j] = pk(kv, kv);
    }

    const float* fp = force + (size_t)plane * (H * W);
    const int gc0 = gx0 + l16 * 4;                     // even
    const float ca = ((unsigned)gc0 < (unsigned)W) ? 1.0f : 0.0f;
    const float cb = ((unsigned)(gc0 + 2) < (unsigned)W) ? 1.0f : 0.0f;

    ull xpa[4], xpb[4], vpa[4], vpb[4];
    float maa[4], mbb[4];

    // ---- init: step 1 analytic (v1 = F*DT, x1 = v1*DT) ----
    #pragma unroll
    for (int i = 0; i < 4; i++) {
        const int gr = gy0 + rb + i;
        float2 fa = make_float2(0.f, 0.f), fb = make_float2(0.f, 0.f);
        if (!edge) {
            fa = *reinterpret_cast<const float2*>(fp + gr * W + gc0);
            fb = *reinterpret_cast<const float2*>(fp + gr * W + gc0 + 2);
        } else {
            const bool rok = (unsigned)gr < (unsigned)H;
            if (rok && ca != 0.0f) fa = *reinterpret_cast<const float2*>(fp + gr * W + gc0);
            if (rok && cb != 0.0f) fb = *reinterpret_cast<const float2*>(fp + gr * W + gc0 + 2);
            const float rm = rok ? 1.0f : 0.0f;
            maa[i] = rm * ca; mbb[i] = rm * cb;
        }
        const ull Fa = pk(fa.x * DTs, fa.y * DTs);
        const ull Fb = pk(fb.x * DTs, fb.y * DTs);
        ulonglong2 fst; fst.x = Fa; fst.y = Fb;
        fs[rb + i][l16] = fst;
        vpa[i] = Fa; vpb[i] = Fb;
        xpa[i] = mul2(Fa, DTp); xpb[i] = mul2(Fb, DTp);
    }
    { ulonglong2 p0; p0.x = xpa[0]; p0.y = xpb[0]; bnd[0][2 * bi + 1][l16] = p0; }
    { ulonglong2 p3; p3.x = xpa[3]; p3.y = xpb[3]; bnd[0][2 * bi + 2][l16] = p3; }
    if (tid < 16) {
        ulonglong2 zz; zz.x = 0; zz.y = 0;
        bnd[0][0][tid] = zz; bnd[1][0][tid] = zz;
    } else if (tid < 32) {
        ulonglong2 zz; zz.x = 0; zz.y = 0;
        bnd[0][33][tid - 16] = zz; bnd[1][33][tid - 16] = zz;
    }
    __syncthreads();

    // ---- mainloop: 5 fused conv+update steps, 1 barrier each ----
    auto mainloop = [&](auto MASKC) {
        constexpr bool MASK = decltype(MASKC)::value;
        #pragma unroll 1
        for (int s = 0; s < 5; s++) {
            ulonglong2 (*cur)[16] = bnd[s & 1];
            ulonglong2 (*nxt)[16] = bnd[(s & 1) ^ 1];

            const ulonglong2 T  = cur[2 * bi][l16];      // row rb-1
            const ulonglong2 Bt = cur[2 * bi + 3][l16];  // row rb+4
            ulonglong2 Fi = fs[rb][l16];
            Line Lt = make_line(T.x, T.y);
            Line Lm = make_line(xpa[0], xpb[0]);

            #pragma unroll
            for (int i = 0; i < 4; i++) {
                const ull ba = (i < 3) ? xpa[i + 1] : Bt.x;
                const ull bb = (i < 3) ? xpb[i + 1] : Bt.y;
                const Line Lb = make_line(ba, bb);     // 2 SHFLs, issued early
                ulonglong2 Fn = Fi;
                if (i < 3) Fn = fs[rb + i + 1][l16];   // prefetch next F

                // pair a (cols c0,c1): two independent chains
                ull a0 = fma2(cbdtp, xpa[i], Fi.x);
                a0 = fma2(kp[0], Lt.La,  a0);
                a0 = fma2(kp[1], Lt.Ca,  a0);
                a0 = fma2(kp[2], Lt.Mid, a0);
                a0 = fma2(kp[3], Lm.La,  a0);
                a0 = fma2(kp[4], xpa[i], a0);
                a0 = fma2(c1p,   vpa[i], a0);
                ull a1 = mul2(kp[5], Lm.Mid);
                a1 = fma2(kp[7], Lb.Ca,  a1);
                a1 = fma2(kp[6], Lb.La,  a1);          // shfl-dependent, late
                a1 = fma2(kp[8], Lb.Mid, a1);
                vpa[i] = add2(a0, a1);

                // pair b (cols c2,c3)
                ull b0 = fma2(cbdtp, xpb[i], Fi.y);
                b0 = fma2(kp[0], Lt.Mid, b0);
                b0 = fma2(kp[1], Lt.Cb,  b0);
                b0 = fma2(kp[2], Lt.Rb,  b0);
                b0 = fma2(kp[3], Lm.Mid, b0);
                b0 = fma2(kp[4], xpb[i], b0);
                b0 = fma2(c1p,   vpb[i], b0);
                ull b1 = mul2(kp[5], Lm.Rb);
                b1 = fma2(kp[7], Lb.Cb,  b1);
                b1 = fma2(kp[6], Lb.Mid, b1);
                b1 = fma2(kp[8], Lb.Rb,  b1);          // shfl-dependent, late
                vpb[i] = add2(b0, b1);

                ull xna = fma2(vpa[i], DTp, xpa[i]);
                ull xnb = fma2(vpb[i], DTp, xpb[i]);
                if (MASK) {
                    xna = mul2(xna, pk(maa[i], maa[i]));
                    xnb = mul2(xnb, pk(mbb[i], mbb[i]));
                }
                Lt = Lm; Lm = Lb;                      // renamed by full unroll
                xpa[i] = xna; xpb[i] = xnb;
                Fi = Fn;
            }
            { ulonglong2 p0; p0.x = xpa[0]; p0.y = xpb[0]; nxt[2 * bi + 1][l16] = p0; }
            { ulonglong2 p3; p3.x = xpa[3]; p3.y = xpb[3]; nxt[2 * bi + 2][l16] = p3; }
            __syncthreads();
        }
    };

    if (edge) mainloop(TrueT{});
    else      mainloop(FalseT{});

    // ---- energy output: region rows [5,58], cols [6,57]; STG.64 per pair ----
    float* op = out + (size_t)plane * (H * W);
    const ull hp   = pk(0.5f, 0.5f);
    const ull hw2p = pk(0.5f * w2, 0.5f * w2);
    const bool pa = (l16 >= 2) && (l16 <= 14) && (ca != 0.0f);
    const bool pb = (l16 >= 1) && (l16 <= 13) && (cb != 0.0f);
    #pragma unroll
    for (int i = 0; i < 4; i++) {
        const int r = rb + i;
        if (r < 5 || r > 58) continue;
        const int gr = gy0 + r;
        if ((unsigned)gr >= (unsigned)H) continue;
        const size_t base = (size_t)gr * W;
        if (pa) {
            const ull e = fma2(hw2p, mul2(xpa[i], xpa[i]), mul2(mul2(vpa[i], vpa[i]), hp));
            *reinterpret_cast<ull*>(op + base + gc0) = e;
        }
        if (pb) {
            const ull e = fma2(hw2p, mul2(xpb[i], xpb[i]), mul2(mul2(vpb[i], vpb[i]), hp));
            *reinterpret_cast<ull*>(op + base + gc0 + 2) = e;
        }
    }
}

extern "C" void kernel_launch(void* const* d_in, const int* in_sizes, int n_in,
                              void* d_out, int out_size)
{
    const float* force = (const float*)d_in[0];
    const float* cw    = (const float*)d_in[1];
    const float* omega = (const float*)d_in[2];
    const float* zeta  = (const float*)d_in[3];
    float* out = (float*)d_out;

    const int H = 256, W = 256;
    const int C = in_sizes[2];
    const int planes = in_sizes[0] / (H * W);

    vib8<<<dim3(5, 5, planes), NTHR>>>(force, cw, omega, zeta, out, H, W, C);
}

// round 9
// speedup vs baseline: 1.5196x; 1.1203x over previous
#include <cuda_runtime.h>
#include <math.h>

typedef unsigned long long ull;

#define DTs   0.2f
#define TILEX 52
#define TILEY 54
#define NTHR  256

// ---- packed f32x2 helpers (sm_103a) ----
__device__ __forceinline__ ull fma2(ull a, ull b, ull c) {
    ull d; asm("fma.rn.f32x2 %0, %1, %2, %3;" : "=l"(d) : "l"(a), "l"(b), "l"(c)); return d;
}
__device__ __forceinline__ ull mul2(ull a, ull b) {
    ull d; asm("mul.rn.f32x2 %0, %1, %2;" : "=l"(d) : "l"(a), "l"(b)); return d;
}
__device__ __forceinline__ ull add2(ull a, ull b) {
    ull d; asm("add.rn.f32x2 %0, %1, %2;" : "=l"(d) : "l"(a), "l"(b)); return d;
}
__device__ __forceinline__ ull pk(float lo, float hi) {
    ull r; asm("mov.b64 %0, {%1, %2};" : "=l"(r) : "f"(lo), "f"(hi)); return r;
}
__device__ __forceinline__ float2 up(ull v) {
    float2 t; asm("mov.b64 {%0, %1}, %2;" : "=f"(t.x), "=f"(t.y) : "l"(v)); return t;
}

struct Line { ull La, Ca, Cb, Rb, Mid; };

// Stencil line from one lane's two pairs a=(c0,c1), b=(c2,c3); edges via
// width-16 shuffles (lane clamp garbage stays in eroded halo).
__device__ __forceinline__ Line make_line(ull a, ull b) {
    const float2 af = up(a), bf = up(b);
    const float el = __shfl_up_sync(0xffffffffu, bf.y, 1, 16);
    const float er = __shfl_down_sync(0xffffffffu, af.x, 1, 16);
    Line L;
    L.La  = pk(el, af.x);
    L.Ca  = a;
    L.Cb  = b;
    L.Mid = pk(af.y, bf.x);
    L.Rb  = pk(bf.y, er);
    return L;
}

__global__ __launch_bounds__(NTHR, 3)
void vib9(const float* __restrict__ force,
          const float* __restrict__ cw,
          const float* __restrict__ omega,
          const float* __restrict__ zeta,
          float* __restrict__ out,
          int H, int W, int C)
{
    __shared__ ulonglong2 bnd[2][34][16];   // boundary rows, double-buffered (+zero guards)
    __shared__ ulonglong2 fs[64][16];       // F*DT^2 pairs

    const int tid  = threadIdx.x;
    const int lane = tid & 31;
    const int l16  = lane & 15;
    const int bi   = ((tid >> 5) << 1) | ((lane >> 4) & 1);  // band 0..15
    const int rb   = bi * 4;

    const int plane = blockIdx.z;
    const int c = plane % C;
    const int bx = blockIdx.x, by = blockIdx.y;

    const int gx0 = bx * TILEX - 6;
    const int gy0 = by * TILEY - 5;

    // per-channel params
    const float o  = __ldg(omega + c);
    const float zt = __ldg(zeta + c);
    const float w  = log1pf(expf(o));
    const float z  = 1.0f / (1.0f + expf(-zt));
    const float w2 = w * w;
    const float c1 = 1.0f - 2.0f * z * w * DTs;
    const float al = 1.0f + c1 - w2 * DTs * DTs;
    const ull alp  = pk(al, al);
    const ull nc1p = pk(-c1, -c1);

    ull kp[9];
    #pragma unroll
    for (int j = 0; j < 9; j++) {
        const float kv = __ldg(cw + c * 9 + j) * (DTs * DTs);  // fold DT^2
        kp[j] = pk(kv, kv);
    }

    const float* fp = force + (size_t)plane * (H * W);
    const int gc0 = gx0 + l16 * 4;
    const float ca = ((unsigned)gc0 < (unsigned)W) ? 1.0f : 0.0f;
    const float cb = ((unsigned)(gc0 + 2) < (unsigned)W) ? 1.0f : 0.0f;

    // two x generations per row-pair; masks (all-ones for interior points)
    ull xa[4], xb[4], pa[4], pb[4];
    float maa[4], mbb[4];

    // ---- init: x1 = F*DT^2, x0 = 0 ----
    #pragma unroll
    for (int i = 0; i < 4; i++) {
        const int gr = gy0 + rb + i;
        const bool rok = (unsigned)gr < (unsigned)H;
        float2 fa = make_float2(0.f, 0.f), fb = make_float2(0.f, 0.f);
        if (rok && ca != 0.0f) fa = *reinterpret_cast<const float2*>(fp + gr * W + gc0);
        if (rok && cb != 0.0f) fb = *reinterpret_cast<const float2*>(fp + gr * W + gc0 + 2);
        const float rm = rok ? 1.0f : 0.0f;
        maa[i] = rm * ca; mbb[i] = rm * cb;
        const ull Fa = pk(fa.x * (DTs * DTs), fa.y * (DTs * DTs));
        const ull Fb = pk(fb.x * (DTs * DTs), fb.y * (DTs * DTs));
        ulonglong2 fst; fst.x = Fa; fst.y = Fb;
        fs[rb + i][l16] = fst;
        xa[i] = Fa; xb[i] = Fb;          // x1
        pa[i] = 0ULL; pb[i] = 0ULL;      // x0
    }
    { ulonglong2 p0; p0.x = xa[0]; p0.y = xb[0]; bnd[0][2 * bi + 1][l16] = p0; }
    { ulonglong2 p3; p3.x = xa[3]; p3.y = xb[3]; bnd[0][2 * bi + 2][l16] = p3; }
    if (tid < 16) {
        ulonglong2 zz; zz.x = 0; zz.y = 0;
        bnd[0][0][tid] = zz; bnd[1][0][tid] = zz;
    } else if (tid < 32) {
        ulonglong2 zz; zz.x = 0; zz.y = 0;
        bnd[0][33][tid - 16] = zz; bnd[1][33][tid - 16] = zz;
    }
    __syncthreads();

    // one step of x-only recurrence: P <- alpha*X - c1*P + (K*DT^2)*X + F*DT^2
    auto step = [&](ull (&Xa)[4], ull (&Xb)[4], ull (&Pa)[4], ull (&Pb)[4], int sb) {
        ulonglong2 (*cur)[16] = bnd[sb];
        ulonglong2 (*nxt)[16] = bnd[sb ^ 1];

        const ulonglong2 T  = cur[2 * bi][l16];      // row rb-1 (X gen)
        const ulonglong2 Bt = cur[2 * bi + 3][l16];  // row rb+4 (X gen)
        ulonglong2 Fi = fs[rb][l16];
        Line Lt = make_line(T.x, T.y);
        Line Lm = make_line(Xa[0], Xb[0]);

        #pragma unroll
        for (int i = 0; i < 4; i++) {
            const ull ba = (i < 3) ? Xa[i + 1] : Bt.x;
            const ull bb = (i < 3) ? Xb[i + 1] : Bt.y;
            const Line Lb = make_line(ba, bb);
            ulonglong2 Fn = Fi;
            if (i < 3) Fn = fs[rb + i + 1][l16];

            // pair a
            ull a0 = fma2(alp, Xa[i], Fi.x);
            a0 = fma2(nc1p, Pa[i], a0);
            a0 = fma2(kp[0], Lt.La,  a0);
            a0 = fma2(kp[1], Lt.Ca,  a0);
            a0 = fma2(kp[2], Lt.Mid, a0);
            a0 = fma2(kp[3], Lm.La,  a0);
            ull a1 = mul2(kp[4], Xa[i]);
            a1 = fma2(kp[5], Lm.Mid, a1);
            a1 = fma2(kp[7], Lb.Ca,  a1);
            a1 = fma2(kp[6], Lb.La,  a1);
            a1 = fma2(kp[8], Lb.Mid, a1);
            Pa[i] = mul2(add2(a0, a1), pk(maa[i], maa[i]));

            // pair b
            ull b0 = fma2(alp, Xb[i], Fi.y);
            b0 = fma2(nc1p, Pb[i], b0);
            b0 = fma2(kp[0], Lt.Mid, b0);
            b0 = fma2(kp[1], Lt.Cb,  b0);
            b0 = fma2(kp[2], Lt.Rb,  b0);
            b0 = fma2(kp[3], Lm.Mid, b0);
            ull b1 = mul2(kp[4], Xb[i]);
            b1 = fma2(kp[5], Lm.Rb,  b1);
            b1 = fma2(kp[7], Lb.Cb,  b1);
            b1 = fma2(kp[6], Lb.Mid, b1);
            b1 = fma2(kp[8], Lb.Rb,  b1);
            Pb[i] = mul2(add2(b0, b1), pk(mbb[i], mbb[i]));

            Lt = Lm; Lm = Lb; Fi = Fn;
        }
        { ulonglong2 p0; p0.x = Pa[0]; p0.y = Pb[0]; nxt[2 * bi + 1][l16] = p0; }
        { ulonglong2 p3; p3.x = Pa[3]; p3.y = Pb[3]; nxt[2 * bi + 2][l16] = p3; }
        __syncthreads();
    };

    // 5 recurrence steps (steps 2..6); parity ping-pongs the generations
    #pragma unroll 1
    for (int s = 0; s < 5; s++) {
        if (s & 1) step(pa, pb, xa, xb, 1);
        else       step(xa, xb, pa, pb, 0);
    }
    // x6 in pa/pb, x5 in xa/xb

    // ---- energy: v6 = (x6-x5)/DT ; E = 0.5 v^2 + 0.5 w2 x6^2 ----
    float* op = out + (size_t)plane * (H * W);
    const ull n1p  = pk(-1.0f, -1.0f);
    const ull qp   = pk(0.5f / (DTs * DTs), 0.5f / (DTs * DTs));
    const ull hw2p = pk(0.5f * w2, 0.5f * w2);
    const bool poka = (l16 >= 2) && (l16 <= 14) && (ca != 0.0f);
    const bool pokb = (l16 >= 1) && (l16 <= 13) && (cb != 0.0f);
    #pragma unroll
    for (int i = 0; i < 4; i++) {
        const int r = rb + i;
        if (r < 5 || r > 58) continue;
        const int gr = gy0 + r;
        if ((unsigned)gr >= (unsigned)H) continue;
        const size_t base = (size_t)gr * W;
        if (poka) {
            const ull d = fma2(n1p, xa[i], pa[i]);           // x6 - x5
            const ull e = fma2(hw2p, mul2(pa[i], pa[i]), mul2(mul2(d, d), qp));
            *reinterpret_cast<ull*>(op + base + gc0) = e;
        }
        if (pokb) {
            const ull d = fma2(n1p, xb[i], pb[i]);
            const ull e = fma2(hw2p, mul2(pb[i], pb[i]), mul2(mul2(d, d), qp));
            *reinterpret_cast<ull*>(op + base + gc0 + 2) = e;
        }
    }
}

extern "C" void kernel_launch(void* const* d_in, const int* in_sizes, int n_in,
                              void* d_out, int out_size)
{
    const float* force = (const float*)d_in[0];
    const float* cw    = (const float*)d_in[1];
    const float* omega = (const float*)d_in[2];
    const float* zeta  = (const float*)d_in[3];
    float* out = (float*)d_out;

    const int H = 256, W = 256;
    const int C = in_sizes[2];
    const int planes = in_sizes[0] / (H * W);

    vib9<<<dim3(5, 5, planes), NTHR>>>(force, cw, omega, zeta, out, H, W, C);
}